// round 1
// baseline (speedup 1.0000x reference)
#include <cuda_runtime.h>

// ---------------- problem constants ----------------
constexpr int Bsz = 4;
constexpr int Np  = 2304;   // H*W = 48*48
constexpr int Cc  = 2304;   // channels = embed
constexpr int Ee  = 2304;
constexpr int E2  = 4608;   // 2*E

// ---------------- scratch (device globals; allocation-free) ----------------
__device__ float g_y1p  [(size_t)Bsz*Cc*2500];        // relu(conv1), zero-padded 50x50
__device__ float g_w2t  [(size_t)9*Cc*Cc];            // conv2 weights re-laid [kk][o][c]
__device__ float g_down [(size_t)Bsz*Cc*Np];
__device__ float g_q    [(size_t)Bsz*Cc*Np];
__device__ float g_k2   [(size_t)Bsz*Cc*Np];
__device__ float g_v2   [(size_t)Bsz*Cc*Np];
__device__ float g_qk   [(size_t)Bsz*Cc*Np];          // qk -> softmax in place
__device__ float g_h1pre[(size_t)Bsz*Cc*Np];          // scatter(ao)+down
__device__ float g_h1   [(size_t)Bsz*Cc*Np];          // after LN1
__device__ float g_f1   [(size_t)Bsz*Cc*(size_t)E2];  // ffn hidden

// ---------------- conv1 (CIN=1) + ReLU, written into padded buffer ----------------
__global__ void conv1_pad_kernel(const float* __restrict__ x,
                                 const float* __restrict__ w1,
                                 const float* __restrict__ b1)
{
    int idx = blockIdx.x * blockDim.x + threadIdx.x;
    if (idx >= Bsz * Cc * 2500) return;
    int pp = idx % 2500;
    int bc = idx / 2500;
    int c  = bc % Cc;
    int b  = bc / Cc;
    int ph = pp / 50, pw = pp % 50;
    float v = 0.f;
    if (ph >= 1 && ph <= 48 && pw >= 1 && pw <= 48) {
        int h = ph - 1, w = pw - 1;
        const float* xb = x + (size_t)b * 2304;
        const float* wc = w1 + (size_t)c * 9;
        float s = b1[c];
        #pragma unroll
        for (int kh = 0; kh < 3; kh++) {
            int hy = h + kh - 1;
            if (hy < 0 || hy >= 48) continue;
            #pragma unroll
            for (int kw = 0; kw < 3; kw++) {
                int wx = w + kw - 1;
                if (wx < 0 || wx >= 48) continue;
                s += wc[kh*3+kw] * xb[hy*48 + wx];
            }
        }
        v = fmaxf(s, 0.f);
    }
    g_y1p[idx] = v;
}

// ---------------- conv2 weight re-layout: w2[o][c][kk] -> w2t[kk][o][c] ----------------
__global__ void w2t_kernel(const float* __restrict__ w2)
{
    __shared__ float sm[2304];
    int base = blockIdx.x * 256;        // (o*Cc+c) row block
    int t = threadIdx.x;
    for (int i = t; i < 2304; i += 256)
        sm[i] = w2[(size_t)base * 9 + i];
    __syncthreads();
    size_t r = (size_t)base + t;
    #pragma unroll
    for (int kk = 0; kk < 9; kk++)
        g_w2t[(size_t)kk * Cc * Cc + r] = sm[t * 9 + kk];
}

// ---------------- conv2 implicit GEMM (+identity, +relu) -> down ----------------
__global__ __launch_bounds__(256) void conv2_kernel(
    const float* __restrict__ x,
    const float* __restrict__ c2b,
    const float* __restrict__ idw,
    const float* __restrict__ idb)
{
    int b = blockIdx.z;
    int row0 = blockIdx.y * 128, col0 = blockIdx.x * 128;
    int tid = threadIdx.x;
    int tx = tid & 15, ty = tid >> 4;
    __shared__ float As[8][128];
    __shared__ float Bs[8][128];
    float acc[8][8] = {};
    const float* Ypb = g_y1p + (size_t)b * Cc * 2500;

    int arow = tid >> 1, akc = (tid & 1) * 4;
    int bk   = tid >> 5, bcol = (tid & 31) * 4;
    int p0c  = col0 + bcol;
    int ph = p0c / 48, pw = p0c - ph * 48;

    #pragma unroll 1
    for (int kk = 0; kk < 9; kk++) {
        int kh = kk / 3, kw = kk - kh * 3;
        const float* Ak = g_w2t + (size_t)kk * Cc * Cc;
        int off0 = (ph + kh) * 50 + pw + kw;
        #pragma unroll 1
        for (int c0 = 0; c0 < Cc; c0 += 8) {
            float4 av = *(const float4*)(Ak + (size_t)(row0 + arow) * Cc + c0 + akc);
            As[akc+0][arow] = av.x; As[akc+1][arow] = av.y;
            As[akc+2][arow] = av.z; As[akc+3][arow] = av.w;
            const float* bp = Ypb + (size_t)(c0 + bk) * 2500 + off0;
            Bs[bk][bcol+0] = bp[0]; Bs[bk][bcol+1] = bp[1];
            Bs[bk][bcol+2] = bp[2]; Bs[bk][bcol+3] = bp[3];
            __syncthreads();
            #pragma unroll
            for (int k = 0; k < 8; k++) {
                float ar[8], br[8];
                *(float4*)&ar[0] = *(const float4*)&As[k][ty*8];
                *(float4*)&ar[4] = *(const float4*)&As[k][ty*8+4];
                *(float4*)&br[0] = *(const float4*)&Bs[k][tx*8];
                *(float4*)&br[4] = *(const float4*)&Bs[k][tx*8+4];
                #pragma unroll
                for (int i = 0; i < 8; i++)
                    #pragma unroll
                    for (int j = 0; j < 8; j++)
                        acc[i][j] = fmaf(ar[i], br[j], acc[i][j]);
            }
            __syncthreads();
        }
    }

    const float* xb = x + (size_t)b * 2304;
    #pragma unroll
    for (int i = 0; i < 8; i++) {
        int o = row0 + ty*8 + i;
        float cb = c2b[o], iw_ = idw[o], ib = idb[o];
        float* dst = g_down + ((size_t)b * Cc + o) * Np;
        #pragma unroll
        for (int j = 0; j < 8; j++) {
            int p = col0 + tx*8 + j;
            float v = acc[i][j] + cb + iw_ * xb[p] + ib;
            dst[p] = fmaxf(v, 0.f);
        }
    }
}

// ---------------- generic 128x128x8 SGEMM with epilogue variants ----------------
// EPI 0: +p0[row]                          (q/k/v bias)
// EPI 1: relu(+p0[col])                    (ffn1)
// EPI 2: +p0[col] + p1[row*ldc+col]        (ffn2 + residual)
// EPI 3: *1/48 + relpos bias               (qk)
// EPI 4: scatter (permute view) + p0[g*N+n] residual (attn@v)
template<int TB, int EPI>
__global__ __launch_bounds__(256) void gemm128(
    const float* __restrict__ Ag, const float* __restrict__ Bg, float* __restrict__ Cg,
    int K, int lda, int ldb, int ldc,
    size_t sA, size_t sB, size_t sC,
    const float* __restrict__ p0, const float* __restrict__ p1)
{
    int b = blockIdx.z;
    const float* A  = Ag + (size_t)b * sA;
    const float* Bm = Bg + (size_t)b * sB;
    float* Cp = Cg + (size_t)b * sC;
    int row0 = blockIdx.y * 128, col0 = blockIdx.x * 128;
    int tid = threadIdx.x;
    int tx = tid & 15, ty = tid >> 4;
    __shared__ float As[8][128];
    __shared__ float Bs[8][128];
    float acc[8][8] = {};
    int arow = tid >> 1, akc = (tid & 1) * 4;
    int bkr  = tid >> 5, bcol = (tid & 31) * 4;

    #pragma unroll 1
    for (int k0 = 0; k0 < K; k0 += 8) {
        float4 av = *(const float4*)(A + (size_t)(row0 + arow) * lda + k0 + akc);
        As[akc+0][arow] = av.x; As[akc+1][arow] = av.y;
        As[akc+2][arow] = av.z; As[akc+3][arow] = av.w;
        if (TB == 0) {
            float4 bv = *(const float4*)(Bm + (size_t)(k0 + bkr) * ldb + col0 + bcol);
            *(float4*)&Bs[bkr][bcol] = bv;
        } else {
            float4 bv = *(const float4*)(Bm + (size_t)(col0 + arow) * ldb + k0 + akc);
            Bs[akc+0][arow] = bv.x; Bs[akc+1][arow] = bv.y;
            Bs[akc+2][arow] = bv.z; Bs[akc+3][arow] = bv.w;
        }
        __syncthreads();
        #pragma unroll
        for (int k = 0; k < 8; k++) {
            float ar[8], br[8];
            *(float4*)&ar[0] = *(const float4*)&As[k][ty*8];
            *(float4*)&ar[4] = *(const float4*)&As[k][ty*8+4];
            *(float4*)&br[0] = *(const float4*)&Bs[k][tx*8];
            *(float4*)&br[4] = *(const float4*)&Bs[k][tx*8+4];
            #pragma unroll
            for (int i = 0; i < 8; i++)
                #pragma unroll
                for (int j = 0; j < 8; j++)
                    acc[i][j] = fmaf(ar[i], br[j], acc[i][j]);
        }
        __syncthreads();
    }

    #pragma unroll
    for (int i = 0; i < 8; i++) {
        int m = row0 + ty*8 + i;
        #pragma unroll
        for (int j = 0; j < 8; j++) {
            int n = col0 + tx*8 + j;
            float v = acc[i][j];
            if (EPI == 0) {
                Cp[(size_t)m * ldc + n] = v + p0[m];
            } else if (EPI == 1) {
                Cp[(size_t)m * ldc + n] = fmaxf(v + p0[n], 0.f);
            } else if (EPI == 2) {
                Cp[(size_t)m * ldc + n] = v + p0[n] + p1[(size_t)m * ldc + n];
            } else if (EPI == 3) {
                v *= 0.0208333333333333f;           // 1/sqrt(2304)
                int ih = m / 48, iw = m - ih * 48;
                int jh = n / 48, jw = n - jh * 48;
                int ridx = (ih - jh + 47) * 95 + (iw - jw + 47);
                Cp[(size_t)m * ldc + n] = v + p0[ridx * 4 + b];
            } else { // EPI 4: permute(1,0,2).view scatter + down residual
                int g = (m / 576) * Cc + (m - (m / 576) * 576) * 4 + b;
                size_t o = (size_t)g * Np + n;
                Cp[o] = v + p0[o];
            }
        }
    }
}

// ---------------- softmax over last dim (2304), in place on g_qk ----------------
__global__ void softmax_kernel()
{
    size_t row = blockIdx.x;
    float* p = g_qk + row * Np;
    int t = threadIdx.x;
    float v[9];
    float mx = -1e30f;
    #pragma unroll
    for (int i = 0; i < 9; i++) { v[i] = p[t + i*256]; mx = fmaxf(mx, v[i]); }
    __shared__ float red[256];
    red[t] = mx; __syncthreads();
    for (int s = 128; s > 0; s >>= 1) {
        if (t < s) red[t] = fmaxf(red[t], red[t+s]);
        __syncthreads();
    }
    mx = red[0]; __syncthreads();
    float sum = 0.f;
    #pragma unroll
    for (int i = 0; i < 9; i++) { v[i] = __expf(v[i] - mx); sum += v[i]; }
    red[t] = sum; __syncthreads();
    for (int s = 128; s > 0; s >>= 1) {
        if (t < s) red[t] += red[t+s];
        __syncthreads();
    }
    float inv = 1.0f / red[0];
    #pragma unroll
    for (int i = 0; i < 9; i++) p[t + i*256] = v[i] * inv;
}

// ---------------- LayerNorm over rows of 2304 ----------------
__global__ void ln_kernel(const float* __restrict__ in, float* __restrict__ out,
                          const float* __restrict__ gam, const float* __restrict__ bet)
{
    size_t row = blockIdx.x;
    const float* p = in + row * Ee;
    float* q = out + row * Ee;
    int t = threadIdx.x;
    float v[9];
    float s = 0.f;
    #pragma unroll
    for (int i = 0; i < 9; i++) { v[i] = p[t + i*256]; s += v[i]; }
    __shared__ float red[256];
    red[t] = s; __syncthreads();
    for (int st = 128; st > 0; st >>= 1) {
        if (t < st) red[t] += red[t+st];
        __syncthreads();
    }
    float mu = red[0] * (1.f / 2304.f); __syncthreads();
    float s2 = 0.f;
    #pragma unroll
    for (int i = 0; i < 9; i++) { float d = v[i] - mu; s2 += d * d; }
    red[t] = s2; __syncthreads();
    for (int st = 128; st > 0; st >>= 1) {
        if (t < st) red[t] += red[t+st];
        __syncthreads();
    }
    float rs = rsqrtf(red[0] * (1.f / 2304.f) + 1e-5f);
    #pragma unroll
    for (int i = 0; i < 9; i++) {
        int n = t + i*256;
        q[n] = (v[i] - mu) * rs * gam[n] + bet[n];
    }
}

// ---------------- maxpool 2x2 ----------------
__global__ void maxpool_kernel(const float* __restrict__ in, float* __restrict__ out)
{
    int idx = blockIdx.x * blockDim.x + threadIdx.x;
    if (idx >= Bsz * Cc * 576) return;
    int r  = idx % 576;
    int bc = idx / 576;
    int i = r / 24, j = r % 24;
    const float* pp = in + (size_t)bc * 2304 + (2*i) * 48 + 2*j;
    out[idx] = fmaxf(fmaxf(pp[0], pp[1]), fmaxf(pp[48], pp[49]));
}

// ---------------- launch ----------------
extern "C" void kernel_launch(void* const* d_in, const int* in_sizes, int n_in,
                              void* d_out, int out_size)
{
    (void)in_sizes; (void)n_in; (void)out_size;
    const float* x       = (const float*)d_in[0];
    const float* conv1_w = (const float*)d_in[1];
    const float* conv1_b = (const float*)d_in[2];
    const float* conv2_w = (const float*)d_in[3];
    const float* conv2_b = (const float*)d_in[4];
    const float* id_w    = (const float*)d_in[5];
    const float* id_b    = (const float*)d_in[6];
    const float* q_w     = (const float*)d_in[7];
    const float* q_b     = (const float*)d_in[8];
    const float* k_w     = (const float*)d_in[9];
    const float* k_b     = (const float*)d_in[10];
    const float* v_w     = (const float*)d_in[11];
    const float* v_b     = (const float*)d_in[12];
    const float* rel_tab = (const float*)d_in[13];
    const float* ln1_g   = (const float*)d_in[14];
    const float* ln1_b   = (const float*)d_in[15];
    const float* ln2_g   = (const float*)d_in[16];
    const float* ln2_b   = (const float*)d_in[17];
    const float* ffn_w1  = (const float*)d_in[18];
    const float* ffn_b1  = (const float*)d_in[19];
    const float* ffn_w2  = (const float*)d_in[20];
    const float* ffn_b2  = (const float*)d_in[21];

    float* out  = (float*)d_out;
    float* pout = out + (size_t)Bsz * Cc * Np;

    float *pdown, *pq, *pk, *pv, *pqk, *ph1pre, *ph1, *pf1;
    cudaGetSymbolAddress((void**)&pdown,  g_down);
    cudaGetSymbolAddress((void**)&pq,     g_q);
    cudaGetSymbolAddress((void**)&pk,     g_k2);
    cudaGetSymbolAddress((void**)&pv,     g_v2);
    cudaGetSymbolAddress((void**)&pqk,    g_qk);
    cudaGetSymbolAddress((void**)&ph1pre, g_h1pre);
    cudaGetSymbolAddress((void**)&ph1,    g_h1);
    cudaGetSymbolAddress((void**)&pf1,    g_f1);

    const size_t sm = (size_t)Cc * Np;   // per-batch plane stride

    conv1_pad_kernel<<<(Bsz*Cc*2500 + 255)/256, 256>>>(x, conv1_w, conv1_b);
    w2t_kernel<<<Cc*Cc/256, 256>>>(conv2_w);
    conv2_kernel<<<dim3(18,18,Bsz), 256>>>(x, conv2_b, id_w, id_b);

    // q,k,v = W @ down + bias     (M=E, K=C, N=Np, batched over B)
    gemm128<0,0><<<dim3(18,18,Bsz), 256>>>(q_w, pdown, pq, Cc, Cc, Np, Np, 0, sm, sm, q_b, nullptr);
    gemm128<0,0><<<dim3(18,18,Bsz), 256>>>(k_w, pdown, pk, Cc, Cc, Np, Np, 0, sm, sm, k_b, nullptr);
    gemm128<0,0><<<dim3(18,18,Bsz), 256>>>(v_w, pdown, pv, Cc, Cc, Np, Np, 0, sm, sm, v_b, nullptr);

    // qk = (q @ k^T)/48 + relpos bias
    gemm128<1,3><<<dim3(18,18,Bsz), 256>>>(pq, pk, pqk, Np, Np, Np, Ee, sm, sm, sm, rel_tab, nullptr);

    softmax_kernel<<<Bsz*Ee, 256>>>();

    // h1pre = scatter(attn @ v) + down
    gemm128<0,4><<<dim3(18,18,Bsz), 256>>>(pqk, pv, ph1pre, Ee, Ee, Np, Np, sm, sm, 0, pdown, nullptr);

    ln_kernel<<<Bsz*Cc, 256>>>(ph1pre, ph1, ln1_g, ln1_b);

    // ffn1: (9216 x 2304) @ (2304 x 4608), relu + bias
    gemm128<0,1><<<dim3(36,72,1), 256>>>(ph1, ffn_w1, pf1, Ee, Ee, E2, E2, 0, 0, 0, ffn_b1, nullptr);
    // ffn2: (9216 x 4608) @ (4608 x 2304) + bias + h1 residual -> d_out (pre-LN2)
    gemm128<0,2><<<dim3(18,72,1), 256>>>(pf1, ffn_w2, out, E2, E2, Np, Np, 0, 0, 0, ffn_b2, ph1);

    ln_kernel<<<Bsz*Cc, 256>>>(out, out, ln2_g, ln2_b);
    maxpool_kernel<<<(Bsz*Cc*576 + 255)/256, 256>>>(out, pout);
}